// round 11
// baseline (speedup 1.0000x reference)
#include <cuda_runtime.h>
#include <math.h>

#define NPTS   131072
#define BATCH  8
#define VIEWS  2
#define HH     1024
#define WW     1024
#define NPIX   (VIEWS * BATCH * HH * WW)   // 16777216
#define FUSED_ELEMS NPIX

#define PT_BLOCKS   (NPTS / 512)           // 256 blocks, 2 points per thread
#define PT_HALF     (NPTS / 2)             // 65536
#define CP_BLOCKS   4096                   // each thread copies 4 float4
#define CP_THREADS  (CP_BLOCKS * 256)      // 1048576

// ---------------- scratch (device globals only; no allocation allowed) ------
// near/far/has statically initialized to their "reset" state; scatter_final_k
// restores that state after consuming them, so every graph replay sees it.
__device__ unsigned int g_near[BATCH * VIEWS] = {
    0x7f800000u,0x7f800000u,0x7f800000u,0x7f800000u,
    0x7f800000u,0x7f800000u,0x7f800000u,0x7f800000u,
    0x7f800000u,0x7f800000u,0x7f800000u,0x7f800000u,
    0x7f800000u,0x7f800000u,0x7f800000u,0x7f800000u};
__device__ unsigned int g_far[BATCH * VIEWS]  = {0};
__device__ int          g_has[BATCH]          = {0};
__device__ int          g_winner[NPIX];             // 64 MB collision-resolution map
__device__ float        g_val[NPTS * 2];
__device__ int          g_pix[NPTS * 2];

// ------- branchless Jacobi rotation on TWO independent 4x4 problems ---------
// Non-skip path executes the EXACT IEEE op sequence of the passing R9 kernel
// (same ops, same order => bitwise-identical results). Skip (|apq|<1e-30)
// becomes a predicated identity instead of a divergent early-return, so the
// whole sweep body is one basic block and ptxas can interleave the two
// independent dependency chains.
template <int P, int Q>
__device__ __forceinline__ void jrot2(float M[2][4][4], float Vv[2][4][4])
{
    float apq[2], app[2], aqq[2], t[2], c[2], s[2];
    bool  skip[2];
#pragma unroll
    for (int u = 0; u < 2; u++) {
        apq[u] = M[u][P][Q];
        skip[u] = fabsf(apq[u]) < 1e-30f;
        app[u] = M[u][P][P];
        aqq[u] = M[u][Q][Q];
        float apqs = skip[u] ? 1.0f : apq[u];
        float tau  = (aqq[u] - app[u]) / (2.0f * apqs);
        float tt   = copysignf(1.0f, tau) / (fabsf(tau) + sqrtf(1.0f + tau * tau));
        float cc   = 1.0f / sqrtf(1.0f + tt * tt);
        t[u] = skip[u] ? 0.0f : tt;
        c[u] = skip[u] ? 1.0f : cc;
        s[u] = skip[u] ? 0.0f : tt * cc;
    }
#pragma unroll
    for (int u = 0; u < 2; u++) {
        M[u][P][P] = app[u] - t[u] * apq[u];
        M[u][Q][Q] = aqq[u] + t[u] * apq[u];
        float offd = skip[u] ? apq[u] : 0.0f;
        M[u][P][Q] = offd; M[u][Q][P] = offd;
#pragma unroll
        for (int k = 0; k < 4; k++) {
            if (k == P || k == Q) continue;
            float mkp = M[u][k][P], mkq = M[u][k][Q];
            float np = c[u] * mkp - s[u] * mkq;
            float nq = s[u] * mkp + c[u] * mkq;
            M[u][k][P] = np; M[u][P][k] = np;
            M[u][k][Q] = nq; M[u][Q][k] = nq;
        }
#pragma unroll
        for (int k = 0; k < 4; k++) {
            float vkp = Vv[u][k][P], vkq = Vv[u][k][Q];
            Vv[u][k][P] = c[u] * vkp - s[u] * vkq;
            Vv[u][k][Q] = s[u] * vkp + c[u] * vkq;
        }
    }
}

// ---------------- K1 (fused): per-block setup + 2 points/thread + copy ------
__global__ void fused_k(const float* __restrict__ mk0,
                        const float* __restrict__ mk1,
                        const float* __restrict__ conf,
                        const int*   __restrict__ bids,
                        const float* __restrict__ intr,
                        const float* __restrict__ extr,
                        const float* __restrict__ disps,
                        float*       __restrict__ out)
{
    if (blockIdx.x >= PT_BLOCKS) {
        // ---- copy path ----
        const float4* in4  = (const float4*)disps;
        float4*       out4 = (float4*)out;
        int i = (blockIdx.x - PT_BLOCKS) * blockDim.x + threadIdx.x;
#pragma unroll
        for (int j = 0; j < 4; j++)
            out4[i + j * CP_THREADS] = in4[i + j * CP_THREADS];
        return;
    }

    // ---- per-block setup: 16 (b,v) projection matrices into SMEM ----
    __shared__ float s_proj[BATCH * VIEWS][12];
    __shared__ float s_row2[BATCH * VIEWS][4];
    if (threadIdx.x < BATCH * VIEWS) {
        int i = threadIdx.x;
        // extrinsics are rigid: E = [R t; 0 0 0 1]  =>  inv = [R^T, -R^T t; 0 1]
        double R[3][3], t[3];
        for (int r = 0; r < 3; r++) {
            for (int c = 0; c < 3; c++) R[r][c] = (double)extr[i * 16 + r * 4 + c];
            t[r] = (double)extr[i * 16 + r * 4 + 3];
        }
        double inv[3][4];
        for (int r = 0; r < 3; r++) {
            inv[r][0] = R[0][r]; inv[r][1] = R[1][r]; inv[r][2] = R[2][r];
            inv[r][3] = -(R[0][r] * t[0] + R[1][r] * t[1] + R[2][r] * t[2]);
        }
        double K[3][3];
        for (int r = 0; r < 3; r++)
            for (int c = 0; c < 3; c++)
                K[r][c] = (double)intr[i * 9 + r * 3 + c];
        for (int c = 0; c < 3; c++) { K[0][c] *= (double)WW; K[1][c] *= (double)HH; }
        for (int r = 0; r < 3; r++)
            for (int c = 0; c < 4; c++) {
                double s = K[r][0] * inv[0][c] + K[r][1] * inv[1][c] + K[r][2] * inv[2][c];
                s_proj[i][r * 4 + c] = (float)s;
            }
        for (int c = 0; c < 4; c++) s_row2[i][c] = (float)inv[2][c];
    }
    __syncthreads();

    // ---- point path: two independent points per thread ----
    int n[2];
    n[0] = blockIdx.x * blockDim.x + threadIdx.x;
    n[1] = n[0] + PT_HALF;

    int    b[2];
    float  cf[2];
    float2 p0[2], p1[2];
    int    pix[2][2];
    float  cost[2][2];
    float  M[2][4][4];
    float  Vv[2][4][4];

#pragma unroll
    for (int u = 0; u < 2; u++) {
        b[u]  = bids[n[u]];
        cf[u] = conf[n[u]];
        p0[u] = reinterpret_cast<const float2*>(mk0)[n[u]];
        p1[u] = reinterpret_cast<const float2*>(mk1)[n[u]];

        // prefetch the random gathers now — their DRAM latency hides under the
        // entire Jacobi chain below.
#pragma unroll
        for (int v = 0; v < 2; v++) {
            float2 p = (v == 0) ? p0[u] : p1[u];
            int x = min(max((int)p.x, 0), WW - 1);
            int y = min(max((int)p.y, 0), HH - 1);
            pix[u][v]  = (((v * BATCH + b[u]) * HH + y) << 10) + x;   // W = 1024
            cost[u][v] = __ldg(&disps[pix[u][v]]);
        }

        const float* P0 = s_proj[b[u] * 2 + 0];
        const float* P1 = s_proj[b[u] * 2 + 1];

        float A[4][4];
#pragma unroll
        for (int k = 0; k < 4; k++) {
            A[0][k] = (P0[8 + k] * p0[u].x - P0[0 + k]) * cf[u];
            A[1][k] = (P0[8 + k] * p0[u].y - P0[4 + k]) * cf[u];
            A[2][k] = (P1[8 + k] * p1[u].x - P1[0 + k]) * cf[u];
            A[3][k] = (P1[8 + k] * p1[u].y - P1[4 + k]) * cf[u];
        }
#pragma unroll
        for (int i = 0; i < 4; i++)
#pragma unroll
            for (int j = i; j < 4; j++) {
                float s = A[0][i] * A[0][j];
                s = fmaf(A[1][i], A[1][j], s);
                s = fmaf(A[2][i], A[2][j], s);
                s = fmaf(A[3][i], A[3][j], s);
                M[u][i][j] = s; M[u][j][i] = s;
            }
#pragma unroll
        for (int i = 0; i < 4; i++)
#pragma unroll
            for (int j = 0; j < 4; j++)
                Vv[u][i][j] = (i == j) ? 1.0f : 0.0f;
    }

#pragma unroll 1
    for (int sweep = 0; sweep < 8; sweep++) {
        jrot2<0,1>(M, Vv); jrot2<0,2>(M, Vv); jrot2<0,3>(M, Vv);
        jrot2<1,2>(M, Vv); jrot2<1,3>(M, Vv); jrot2<2,3>(M, Vv);
    }

#pragma unroll
    for (int u = 0; u < 2; u++) {
        // min-eigenvalue column via static predicated selects
        float dm = M[u][0][0];
        float h0 = Vv[u][0][0], h1 = Vv[u][1][0], h2 = Vv[u][2][0], h3 = Vv[u][3][0];
#pragma unroll
        for (int j = 1; j < 4; j++) {
            bool lt = M[u][j][j] < dm;
            dm = lt ? M[u][j][j] : dm;
            h0 = lt ? Vv[u][0][j] : h0;
            h1 = lt ? Vv[u][1][j] : h1;
            h2 = lt ? Vv[u][2][j] : h2;
            h3 = lt ? Vv[u][3][j] : h3;
        }
        float px = h0 / h3, py = h1 / h3, pz = h2 / h3;

        const float* r20 = s_row2[b[u] * 2 + 0];
        const float* r21 = s_row2[b[u] * 2 + 1];
        float z0 = fmaf(r20[0], px, fmaf(r20[1], py, fmaf(r20[2], pz, r20[3])));
        float z1 = fmaf(r21[0], px, fmaf(r21[1], py, fmaf(r21[2], pz, r21[3])));

        bool valid = (z0 > 0.0f) && (z0 < 500.0f) && (z1 > 0.0f) && (z1 < 500.0f);
        if (valid) {
            atomicMin(&g_near[b[u] * 2 + 0], __float_as_uint(z0));
            atomicMin(&g_near[b[u] * 2 + 1], __float_as_uint(z1));
            atomicMax(&g_far [b[u] * 2 + 0], __float_as_uint(z0));
            atomicMax(&g_far [b[u] * 2 + 1], __float_as_uint(z1));
            g_has[b[u]] = 1;
        }

#pragma unroll
        for (int v = 0; v < 2; v++) {
            float z   = (v == 0) ? z0 : z1;
            float val = valid ? (0.5f * (1.0f / z) + 0.5f * cost[u][v]) : cost[u][v];
            g_val[n[u] * 2 + v] = val;
            g_pix[n[u] * 2 + v] = pix[u][v];
            g_winner[pix[u][v]] = -1;   // clear only touched pixels
        }
    }
}

// ---------------- K2: collision winner = max point index --------------------
__global__ void winner_k()
{
    int i = blockIdx.x * blockDim.x + threadIdx.x;
    if (i >= NPTS * 2) return;
    atomicMax(&g_winner[g_pix[i]], i >> 1);
}

// ---------------- K3: scatter winners + near/far/flag tail (+self-reset) ----
__global__ void scatter_final_k(float* __restrict__ out)
{
    int i = blockIdx.x * blockDim.x + threadIdx.x;
    if (i < NPTS * 2) {
        int pix = g_pix[i];
        if (g_winner[pix] == (i >> 1)) out[pix] = g_val[i];
    }
    if (blockIdx.x == 0 && threadIdx.x < BATCH * VIEWS) {
        int t = threadIdx.x;
        int has = g_has[t >> 1];
        out[FUSED_ELEMS +  0 + t] = has ? __uint_as_float(g_near[t]) : 0.0f;
        out[FUSED_ELEMS + 16 + t] = has ? __uint_as_float(g_far[t])  : 500.0f;
        out[FUSED_ELEMS + 32 + t] = has ? 1.0f : 0.0f;
        // restore reset-state invariant for the next graph replay.
        g_near[t] = 0x7f800000u;
        g_far[t]  = 0u;
        if (t < BATCH) g_has[t] = 0;
    }
}

// ---------------- launch -----------------------------------------------------
extern "C" void kernel_launch(void* const* d_in, const int* in_sizes, int n_in,
                              void* d_out, int out_size)
{
    const float* mk0   = (const float*)d_in[0];
    const float* mk1   = (const float*)d_in[1];
    const float* conf  = (const float*)d_in[2];
    const int*   bids  = (const int*)  d_in[3];
    const float* intr  = (const float*)d_in[4];
    const float* extr  = (const float*)d_in[5];
    const float* disps = (const float*)d_in[6];
    float* out = (float*)d_out;

    fused_k        <<<PT_BLOCKS + CP_BLOCKS, 256>>>(mk0, mk1, conf, bids, intr, extr, disps, out);
    winner_k       <<<(NPTS * 2) / 256, 256>>>();
    scatter_final_k<<<(NPTS * 2) / 256, 256>>>(out);
}

// round 12
// speedup vs baseline: 1.2941x; 1.2941x over previous
#include <cuda_runtime.h>
#include <math.h>

#define NPTS   131072
#define BATCH  8
#define VIEWS  2
#define HH     1024
#define WW     1024
#define NPIX   (VIEWS * BATCH * HH * WW)   // 16777216
#define FUSED_ELEMS NPIX

#define PT_BLOCKS   (NPTS / 256)           // 512
#define CP_BLOCKS   4096                   // each thread copies 4 float4
#define CP_THREADS  (CP_BLOCKS * 256)      // 1048576

// ---------------- scratch (device globals only; no allocation allowed) ------
__device__ unsigned int g_near[BATCH * VIEWS] = {
    0x7f800000u,0x7f800000u,0x7f800000u,0x7f800000u,
    0x7f800000u,0x7f800000u,0x7f800000u,0x7f800000u,
    0x7f800000u,0x7f800000u,0x7f800000u,0x7f800000u,
    0x7f800000u,0x7f800000u,0x7f800000u,0x7f800000u};
__device__ unsigned int g_far[BATCH * VIEWS]  = {0};
__device__ int          g_has[BATCH]          = {0};
__device__ int          g_winner[NPIX];             // 64 MB collision-resolution map
__device__ float        g_val[NPTS * 2];
__device__ int          g_pix[NPTS * 2];

// ---------------- Jacobi rotation on 4x4 symmetric, fixed (P,Q) -------------
// EXACT R9 arithmetic: IEEE div/sqrt, divergent early-skip (the skip SAVES
// work in late sweeps). Do not touch — every variant (approx, NR-refined,
// branchless) moved rel_err by >1.8x through the ill-conditioned points.
template <int P, int Q>
__device__ __forceinline__ void jrot(float M[4][4], float Vv[4][4])
{
    float apq = M[P][Q];
    if (fabsf(apq) < 1e-30f) return;
    float app = M[P][P], aqq = M[Q][Q];
    float tau = (aqq - app) / (2.0f * apq);
    float t = copysignf(1.0f, tau) / (fabsf(tau) + sqrtf(1.0f + tau * tau));
    float c = 1.0f / sqrtf(1.0f + t * t);
    float s = t * c;
    M[P][P] = app - t * apq;
    M[Q][Q] = aqq + t * apq;
    M[P][Q] = 0.0f; M[Q][P] = 0.0f;
#pragma unroll
    for (int k = 0; k < 4; k++) {
        if (k == P || k == Q) continue;
        float mkp = M[k][P], mkq = M[k][Q];
        float np = c * mkp - s * mkq;
        float nq = s * mkp + c * mkq;
        M[k][P] = np; M[P][k] = np;
        M[k][Q] = nq; M[Q][k] = nq;
    }
#pragma unroll
    for (int k = 0; k < 4; k++) {
        float vkp = Vv[k][P], vkq = Vv[k][Q];
        Vv[k][P] = c * vkp - s * vkq;
        Vv[k][Q] = s * vkp + c * vkq;
    }
}

// ---------------- K1 (fused): per-block setup + points + bulk copy ----------
// __launch_bounds__(256, 3): allow up to ~85 regs so the Jacobi working set
// (M 16 + Vv 16 + scalars) NEVER spills to local — R9's 56-reg allocation sat
// at the spill edge and the rotation loop paid LDL/STL latency per access.
__global__ void __launch_bounds__(256, 3)
fused_k(const float* __restrict__ mk0,
        const float* __restrict__ mk1,
        const float* __restrict__ conf,
        const int*   __restrict__ bids,
        const float* __restrict__ intr,
        const float* __restrict__ extr,
        const float* __restrict__ disps,
        float*       __restrict__ out)
{
    if (blockIdx.x >= PT_BLOCKS) {
        // ---- copy path ----
        const float4* in4  = (const float4*)disps;
        float4*       out4 = (float4*)out;
        int i = (blockIdx.x - PT_BLOCKS) * blockDim.x + threadIdx.x;
#pragma unroll
        for (int j = 0; j < 4; j++)
            out4[i + j * CP_THREADS] = in4[i + j * CP_THREADS];
        return;
    }

    // ---- per-block setup: 16 (b,v) projection matrices into SMEM ----
    __shared__ float s_proj[BATCH * VIEWS][12];
    __shared__ float s_row2[BATCH * VIEWS][4];
    if (threadIdx.x < BATCH * VIEWS) {
        int i = threadIdx.x;
        // extrinsics are rigid: E = [R t; 0 0 0 1]  =>  inv = [R^T, -R^T t; 0 1]
        double R[3][3], t[3];
        for (int r = 0; r < 3; r++) {
            for (int c = 0; c < 3; c++) R[r][c] = (double)extr[i * 16 + r * 4 + c];
            t[r] = (double)extr[i * 16 + r * 4 + 3];
        }
        double inv[3][4];
        for (int r = 0; r < 3; r++) {
            inv[r][0] = R[0][r]; inv[r][1] = R[1][r]; inv[r][2] = R[2][r];
            inv[r][3] = -(R[0][r] * t[0] + R[1][r] * t[1] + R[2][r] * t[2]);
        }
        double K[3][3];
        for (int r = 0; r < 3; r++)
            for (int c = 0; c < 3; c++)
                K[r][c] = (double)intr[i * 9 + r * 3 + c];
        for (int c = 0; c < 3; c++) { K[0][c] *= (double)WW; K[1][c] *= (double)HH; }
        for (int r = 0; r < 3; r++)
            for (int c = 0; c < 4; c++) {
                double s = K[r][0] * inv[0][c] + K[r][1] * inv[1][c] + K[r][2] * inv[2][c];
                s_proj[i][r * 4 + c] = (float)s;
            }
        for (int c = 0; c < 4; c++) s_row2[i][c] = (float)inv[2][c];
    }
    __syncthreads();

    // ---- point path ----
    int n = blockIdx.x * blockDim.x + threadIdx.x;

    int   b  = bids[n];
    float cf = conf[n];
    float2 p0 = reinterpret_cast<const float2*>(mk0)[n];
    float2 p1 = reinterpret_cast<const float2*>(mk1)[n];

    // prefetch random gathers; latency hides under the Jacobi chain.
    int   pix0, pix1;
    float cost0, cost1;
    {
        int x0 = min(max((int)p0.x, 0), WW - 1);
        int y0 = min(max((int)p0.y, 0), HH - 1);
        pix0 = ((b * HH + y0) << 10) + x0;                      // v=0
        int x1 = min(max((int)p1.x, 0), WW - 1);
        int y1 = min(max((int)p1.y, 0), HH - 1);
        pix1 = (((BATCH + b) * HH + y1) << 10) + x1;            // v=1
        cost0 = __ldg(&disps[pix0]);
        cost1 = __ldg(&disps[pix1]);
    }

    const float* P0 = s_proj[b * 2 + 0];
    const float* P1 = s_proj[b * 2 + 1];

    // M = A^T A accumulated ROW-WISE (A rows never all live at once).
    // fmaf chain order per element identical to R9: row0 (mul), then rows 1-3.
    float M[4][4];
    {
        float a0[4], a1[4], a2[4], a3[4];
#pragma unroll
        for (int k = 0; k < 4; k++) a0[k] = (P0[8 + k] * p0.x - P0[0 + k]) * cf;
#pragma unroll
        for (int k = 0; k < 4; k++) a1[k] = (P0[8 + k] * p0.y - P0[4 + k]) * cf;
#pragma unroll
        for (int i = 0; i < 4; i++)
#pragma unroll
            for (int j = i; j < 4; j++)
                M[i][j] = fmaf(a1[i], a1[j], a0[i] * a0[j]);
#pragma unroll
        for (int k = 0; k < 4; k++) a2[k] = (P1[8 + k] * p1.x - P1[0 + k]) * cf;
#pragma unroll
        for (int i = 0; i < 4; i++)
#pragma unroll
            for (int j = i; j < 4; j++)
                M[i][j] = fmaf(a2[i], a2[j], M[i][j]);
#pragma unroll
        for (int k = 0; k < 4; k++) a3[k] = (P1[8 + k] * p1.y - P1[4 + k]) * cf;
#pragma unroll
        for (int i = 0; i < 4; i++)
#pragma unroll
            for (int j = i; j < 4; j++) {
                M[i][j] = fmaf(a3[i], a3[j], M[i][j]);
                M[j][i] = M[i][j];
            }
    }

    float Vv[4][4] = {{1,0,0,0},{0,1,0,0},{0,0,1,0},{0,0,0,1}};

#pragma unroll 1
    for (int sweep = 0; sweep < 8; sweep++) {
        jrot<0,1>(M, Vv); jrot<0,2>(M, Vv); jrot<0,3>(M, Vv);
        jrot<1,2>(M, Vv); jrot<1,3>(M, Vv); jrot<2,3>(M, Vv);
    }

    // min-eigenvalue column via static predicated selects (register-resident)
    float dm = M[0][0];
    float h0 = Vv[0][0], h1 = Vv[1][0], h2 = Vv[2][0], h3 = Vv[3][0];
#pragma unroll
    for (int j = 1; j < 4; j++) {
        bool lt = M[j][j] < dm;
        dm = lt ? M[j][j] : dm;
        h0 = lt ? Vv[0][j] : h0;
        h1 = lt ? Vv[1][j] : h1;
        h2 = lt ? Vv[2][j] : h2;
        h3 = lt ? Vv[3][j] : h3;
    }
    float px = h0 / h3, py = h1 / h3, pz = h2 / h3;

    const float* r20 = s_row2[b * 2 + 0];
    const float* r21 = s_row2[b * 2 + 1];
    float z0 = fmaf(r20[0], px, fmaf(r20[1], py, fmaf(r20[2], pz, r20[3])));
    float z1 = fmaf(r21[0], px, fmaf(r21[1], py, fmaf(r21[2], pz, r21[3])));

    bool valid = (z0 > 0.0f) && (z0 < 500.0f) && (z1 > 0.0f) && (z1 < 500.0f);
    if (valid) {
        atomicMin(&g_near[b * 2 + 0], __float_as_uint(z0));
        atomicMin(&g_near[b * 2 + 1], __float_as_uint(z1));
        atomicMax(&g_far [b * 2 + 0], __float_as_uint(z0));
        atomicMax(&g_far [b * 2 + 1], __float_as_uint(z1));
        g_has[b] = 1;
    }

    {
        float val0 = valid ? (0.5f * (1.0f / z0) + 0.5f * cost0) : cost0;
        float val1 = valid ? (0.5f * (1.0f / z1) + 0.5f * cost1) : cost1;
        g_val[n * 2 + 0] = val0;
        g_val[n * 2 + 1] = val1;
        g_pix[n * 2 + 0] = pix0;
        g_pix[n * 2 + 1] = pix1;
        g_winner[pix0]   = -1;   // clear only touched pixels
        g_winner[pix1]   = -1;
    }
}

// ---------------- K2: collision winner = max point index --------------------
__global__ void winner_k()
{
    int i = blockIdx.x * blockDim.x + threadIdx.x;
    if (i >= NPTS * 2) return;
    atomicMax(&g_winner[g_pix[i]], i >> 1);
}

// ---------------- K3: scatter winners + near/far/flag tail (+self-reset) ----
__global__ void scatter_final_k(float* __restrict__ out)
{
    int i = blockIdx.x * blockDim.x + threadIdx.x;
    if (i < NPTS * 2) {
        int pix = g_pix[i];
        if (g_winner[pix] == (i >> 1)) out[pix] = g_val[i];
    }
    if (blockIdx.x == 0 && threadIdx.x < BATCH * VIEWS) {
        int t = threadIdx.x;
        int has = g_has[t >> 1];
        out[FUSED_ELEMS +  0 + t] = has ? __uint_as_float(g_near[t]) : 0.0f;
        out[FUSED_ELEMS + 16 + t] = has ? __uint_as_float(g_far[t])  : 500.0f;
        out[FUSED_ELEMS + 32 + t] = has ? 1.0f : 0.0f;
        // restore reset-state invariant for the next graph replay.
        g_near[t] = 0x7f800000u;
        g_far[t]  = 0u;
        if (t < BATCH) g_has[t] = 0;
    }
}

// ---------------- launch -----------------------------------------------------
extern "C" void kernel_launch(void* const* d_in, const int* in_sizes, int n_in,
                              void* d_out, int out_size)
{
    const float* mk0   = (const float*)d_in[0];
    const float* mk1   = (const float*)d_in[1];
    const float* conf  = (const float*)d_in[2];
    const int*   bids  = (const int*)  d_in[3];
    const float* intr  = (const float*)d_in[4];
    const float* extr  = (const float*)d_in[5];
    const float* disps = (const float*)d_in[6];
    float* out = (float*)d_out;

    fused_k        <<<PT_BLOCKS + CP_BLOCKS, 256>>>(mk0, mk1, conf, bids, intr, extr, disps, out);
    winner_k       <<<(NPTS * 2) / 256, 256>>>();
    scatter_final_k<<<(NPTS * 2) / 256, 256>>>(out);
}

// round 13
// speedup vs baseline: 1.3794x; 1.0659x over previous
#include <cuda_runtime.h>
#include <math.h>

#define NPTS   131072
#define BATCH  8
#define VIEWS  2
#define HH     1024
#define WW     1024
#define NPIX   (VIEWS * BATCH * HH * WW)   // 16777216
#define FUSED_ELEMS NPIX

#define PT_BLOCKS   (NPTS / 256)           // 512
#define CP_BLOCKS   4096                   // each thread copies 4 float4
#define CP_THREADS  (CP_BLOCKS * 256)      // 1048576

// ---------------- scratch (device globals only; no allocation allowed) ------
__device__ unsigned int g_near[BATCH * VIEWS] = {
    0x7f800000u,0x7f800000u,0x7f800000u,0x7f800000u,
    0x7f800000u,0x7f800000u,0x7f800000u,0x7f800000u,
    0x7f800000u,0x7f800000u,0x7f800000u,0x7f800000u,
    0x7f800000u,0x7f800000u,0x7f800000u,0x7f800000u};
__device__ unsigned int g_far[BATCH * VIEWS]  = {0};
__device__ int          g_has[BATCH]          = {0};
__device__ int          g_winner[NPIX];             // 64 MB collision-resolution map
__device__ float        g_val[NPTS * 2];
__device__ int          g_pix[NPTS * 2];

// ---------------- Jacobi rotation on 4x4 symmetric, fixed (P,Q) -------------
// Executed path is the EXACT R9 IEEE sequence (bitwise-identical results).
// The ONLY change: skip threshold is RELATIVE (thr = eps * trace(M)).
// M has norm ~1e12, so the old 1e-30 absolute threshold NEVER fired and all
// 48 rotations burned 5 MUFU ops each rotating on fp32 rounding noise.
// Rotations with |apq| < eps*tr have angle <~1e-7 — below the noise floor any
// fp32 Jacobi stalls at; skipping them perturbs V by ~1e-7 each (~1e-5 total).
template <int P, int Q>
__device__ __forceinline__ void jrot(float M[4][4], float Vv[4][4], float thr)
{
    float apq = M[P][Q];
    if (fabsf(apq) < thr) return;
    float app = M[P][P], aqq = M[Q][Q];
    float tau = (aqq - app) / (2.0f * apq);
    float t = copysignf(1.0f, tau) / (fabsf(tau) + sqrtf(1.0f + tau * tau));
    float c = 1.0f / sqrtf(1.0f + t * t);
    float s = t * c;
    M[P][P] = app - t * apq;
    M[Q][Q] = aqq + t * apq;
    M[P][Q] = 0.0f; M[Q][P] = 0.0f;
#pragma unroll
    for (int k = 0; k < 4; k++) {
        if (k == P || k == Q) continue;
        float mkp = M[k][P], mkq = M[k][Q];
        float np = c * mkp - s * mkq;
        float nq = s * mkp + c * mkq;
        M[k][P] = np; M[P][k] = np;
        M[k][Q] = nq; M[Q][k] = nq;
    }
#pragma unroll
    for (int k = 0; k < 4; k++) {
        float vkp = Vv[k][P], vkq = Vv[k][Q];
        Vv[k][P] = c * vkp - s * vkq;
        Vv[k][Q] = s * vkp + c * vkq;
    }
}

// ---------------- K1 (fused): per-block setup + points + bulk copy ----------
__global__ void fused_k(const float* __restrict__ mk0,
                        const float* __restrict__ mk1,
                        const float* __restrict__ conf,
                        const int*   __restrict__ bids,
                        const float* __restrict__ intr,
                        const float* __restrict__ extr,
                        const float* __restrict__ disps,
                        float*       __restrict__ out)
{
    if (blockIdx.x >= PT_BLOCKS) {
        // ---- copy path ----
        const float4* in4  = (const float4*)disps;
        float4*       out4 = (float4*)out;
        int i = (blockIdx.x - PT_BLOCKS) * blockDim.x + threadIdx.x;
#pragma unroll
        for (int j = 0; j < 4; j++)
            out4[i + j * CP_THREADS] = in4[i + j * CP_THREADS];
        return;
    }

    // ---- per-block setup: 16 (b,v) projection matrices into SMEM ----
    __shared__ float s_proj[BATCH * VIEWS][12];
    __shared__ float s_row2[BATCH * VIEWS][4];
    if (threadIdx.x < BATCH * VIEWS) {
        int i = threadIdx.x;
        // extrinsics are rigid: E = [R t; 0 0 0 1]  =>  inv = [R^T, -R^T t; 0 1]
        double R[3][3], t[3];
        for (int r = 0; r < 3; r++) {
            for (int c = 0; c < 3; c++) R[r][c] = (double)extr[i * 16 + r * 4 + c];
            t[r] = (double)extr[i * 16 + r * 4 + 3];
        }
        double inv[3][4];
        for (int r = 0; r < 3; r++) {
            inv[r][0] = R[0][r]; inv[r][1] = R[1][r]; inv[r][2] = R[2][r];
            inv[r][3] = -(R[0][r] * t[0] + R[1][r] * t[1] + R[2][r] * t[2]);
        }
        double K[3][3];
        for (int r = 0; r < 3; r++)
            for (int c = 0; c < 3; c++)
                K[r][c] = (double)intr[i * 9 + r * 3 + c];
        for (int c = 0; c < 3; c++) { K[0][c] *= (double)WW; K[1][c] *= (double)HH; }
        for (int r = 0; r < 3; r++)
            for (int c = 0; c < 4; c++) {
                double s = K[r][0] * inv[0][c] + K[r][1] * inv[1][c] + K[r][2] * inv[2][c];
                s_proj[i][r * 4 + c] = (float)s;
            }
        for (int c = 0; c < 4; c++) s_row2[i][c] = (float)inv[2][c];
    }
    __syncthreads();

    // ---- point path ----
    int n = blockIdx.x * blockDim.x + threadIdx.x;

    int   b  = bids[n];
    float cf = conf[n];
    float2 p0 = reinterpret_cast<const float2*>(mk0)[n];
    float2 p1 = reinterpret_cast<const float2*>(mk1)[n];

    // prefetch random gathers; their DRAM latency hides under the Jacobi chain.
    int   pix0, pix1;
    float cost0, cost1;
    {
        int x0 = min(max((int)p0.x, 0), WW - 1);
        int y0 = min(max((int)p0.y, 0), HH - 1);
        pix0 = ((b * HH + y0) << 10) + x0;                      // v=0
        int x1 = min(max((int)p1.x, 0), WW - 1);
        int y1 = min(max((int)p1.y, 0), HH - 1);
        pix1 = (((BATCH + b) * HH + y1) << 10) + x1;            // v=1
        cost0 = __ldg(&disps[pix0]);
        cost1 = __ldg(&disps[pix1]);
    }

    const float* P0 = s_proj[b * 2 + 0];
    const float* P1 = s_proj[b * 2 + 1];

    float A[4][4];
#pragma unroll
    for (int k = 0; k < 4; k++) {
        A[0][k] = (P0[8 + k] * p0.x - P0[0 + k]) * cf;
        A[1][k] = (P0[8 + k] * p0.y - P0[4 + k]) * cf;
        A[2][k] = (P1[8 + k] * p1.x - P1[0 + k]) * cf;
        A[3][k] = (P1[8 + k] * p1.y - P1[4 + k]) * cf;
    }

    float M[4][4];
#pragma unroll
    for (int i = 0; i < 4; i++)
#pragma unroll
        for (int j = i; j < 4; j++) {
            float s = A[0][i] * A[0][j];
            s = fmaf(A[1][i], A[1][j], s);
            s = fmaf(A[2][i], A[2][j], s);
            s = fmaf(A[3][i], A[3][j], s);
            M[i][j] = s; M[j][i] = s;
        }

    // relative convergence threshold: eps * trace (trace is rotation-invariant)
    float thr = 1.1920929e-7f * (M[0][0] + M[1][1] + M[2][2] + M[3][3]);

    float Vv[4][4] = {{1,0,0,0},{0,1,0,0},{0,0,1,0},{0,0,0,1}};

#pragma unroll 1
    for (int sweep = 0; sweep < 8; sweep++) {
        jrot<0,1>(M, Vv, thr); jrot<0,2>(M, Vv, thr); jrot<0,3>(M, Vv, thr);
        jrot<1,2>(M, Vv, thr); jrot<1,3>(M, Vv, thr); jrot<2,3>(M, Vv, thr);
    }

    // min-eigenvalue column via static predicated selects (register-resident)
    float dm = M[0][0];
    float h0 = Vv[0][0], h1 = Vv[1][0], h2 = Vv[2][0], h3 = Vv[3][0];
#pragma unroll
    for (int j = 1; j < 4; j++) {
        bool lt = M[j][j] < dm;
        dm = lt ? M[j][j] : dm;
        h0 = lt ? Vv[0][j] : h0;
        h1 = lt ? Vv[1][j] : h1;
        h2 = lt ? Vv[2][j] : h2;
        h3 = lt ? Vv[3][j] : h3;
    }
    float px = h0 / h3, py = h1 / h3, pz = h2 / h3;

    const float* r20 = s_row2[b * 2 + 0];
    const float* r21 = s_row2[b * 2 + 1];
    float z0 = fmaf(r20[0], px, fmaf(r20[1], py, fmaf(r20[2], pz, r20[3])));
    float z1 = fmaf(r21[0], px, fmaf(r21[1], py, fmaf(r21[2], pz, r21[3])));

    bool valid = (z0 > 0.0f) && (z0 < 500.0f) && (z1 > 0.0f) && (z1 < 500.0f);
    if (valid) {
        atomicMin(&g_near[b * 2 + 0], __float_as_uint(z0));
        atomicMin(&g_near[b * 2 + 1], __float_as_uint(z1));
        atomicMax(&g_far [b * 2 + 0], __float_as_uint(z0));
        atomicMax(&g_far [b * 2 + 1], __float_as_uint(z1));
        g_has[b] = 1;
    }

    {
        float val0 = valid ? (0.5f * (1.0f / z0) + 0.5f * cost0) : cost0;
        float val1 = valid ? (0.5f * (1.0f / z1) + 0.5f * cost1) : cost1;
        g_val[n * 2 + 0] = val0;
        g_val[n * 2 + 1] = val1;
        g_pix[n * 2 + 0] = pix0;
        g_pix[n * 2 + 1] = pix1;
        g_winner[pix0]   = -1;   // clear only touched pixels
        g_winner[pix1]   = -1;
    }
}

// ---------------- K2: collision winner = max point index --------------------
__global__ void winner_k()
{
    int i = blockIdx.x * blockDim.x + threadIdx.x;
    if (i >= NPTS * 2) return;
    atomicMax(&g_winner[g_pix[i]], i >> 1);
}

// ---------------- K3: scatter winners + near/far/flag tail (+self-reset) ----
__global__ void scatter_final_k(float* __restrict__ out)
{
    int i = blockIdx.x * blockDim.x + threadIdx.x;
    if (i < NPTS * 2) {
        int pix = g_pix[i];
        if (g_winner[pix] == (i >> 1)) out[pix] = g_val[i];
    }
    if (blockIdx.x == 0 && threadIdx.x < BATCH * VIEWS) {
        int t = threadIdx.x;
        int has = g_has[t >> 1];
        out[FUSED_ELEMS +  0 + t] = has ? __uint_as_float(g_near[t]) : 0.0f;
        out[FUSED_ELEMS + 16 + t] = has ? __uint_as_float(g_far[t])  : 500.0f;
        out[FUSED_ELEMS + 32 + t] = has ? 1.0f : 0.0f;
        // restore reset-state invariant for the next graph replay.
        g_near[t] = 0x7f800000u;
        g_far[t]  = 0u;
        if (t < BATCH) g_has[t] = 0;
    }
}

// ---------------- launch -----------------------------------------------------
extern "C" void kernel_launch(void* const* d_in, const int* in_sizes, int n_in,
                              void* d_out, int out_size)
{
    const float* mk0   = (const float*)d_in[0];
    const float* mk1   = (const float*)d_in[1];
    const float* conf  = (const float*)d_in[2];
    const int*   bids  = (const int*)  d_in[3];
    const float* intr  = (const float*)d_in[4];
    const float* extr  = (const float*)d_in[5];
    const float* disps = (const float*)d_in[6];
    float* out = (float*)d_out;

    fused_k        <<<PT_BLOCKS + CP_BLOCKS, 256>>>(mk0, mk1, conf, bids, intr, extr, disps, out);
    winner_k       <<<(NPTS * 2) / 256, 256>>>();
    scatter_final_k<<<(NPTS * 2) / 256, 256>>>(out);
}

// round 14
// speedup vs baseline: 2.8986x; 2.1014x over previous
#include <cuda_runtime.h>
#include <math.h>

#define NPTS   131072
#define BATCH  8
#define VIEWS  2
#define HH     1024
#define WW     1024
#define NPIX   (VIEWS * BATCH * HH * WW)   // 16777216
#define FUSED_ELEMS NPIX

#define PT_BLOCKS   (NPTS / 256)           // 512
#define CP_BLOCKS   4096                   // each thread copies 4 float4
#define CP_THREADS  (CP_BLOCKS * 256)      // 1048576

// ---------------- scratch (device globals only; no allocation allowed) ------
__device__ unsigned int g_near[BATCH * VIEWS] = {
    0x7f800000u,0x7f800000u,0x7f800000u,0x7f800000u,
    0x7f800000u,0x7f800000u,0x7f800000u,0x7f800000u,
    0x7f800000u,0x7f800000u,0x7f800000u,0x7f800000u,
    0x7f800000u,0x7f800000u,0x7f800000u,0x7f800000u};
__device__ unsigned int g_far[BATCH * VIEWS]  = {0};
__device__ int          g_has[BATCH]          = {0};
__device__ int          g_winner[NPIX];             // 64 MB collision-resolution map
__device__ float        g_val[NPTS * 2];
__device__ int          g_pix[NPTS * 2];

// ---------------- Jacobi rotation on 4x4 symmetric, fixed (P,Q) -------------
// Executed path: EXACT IEEE sequence (best-known accuracy, rel_err 7.945e-4).
// Relative skip threshold (eps*trace) — converged rotations skip instead of
// burning MUFU on rounding noise.
template <int P, int Q>
__device__ __forceinline__ void jrot(float M[4][4], float Vv[4][4], float thr)
{
    float apq = M[P][Q];
    if (fabsf(apq) < thr) return;
    float app = M[P][P], aqq = M[Q][Q];
    float tau = (aqq - app) / (2.0f * apq);
    float t = copysignf(1.0f, tau) / (fabsf(tau) + sqrtf(1.0f + tau * tau));
    float c = 1.0f / sqrtf(1.0f + t * t);
    float s = t * c;
    M[P][P] = app - t * apq;
    M[Q][Q] = aqq + t * apq;
    M[P][Q] = 0.0f; M[Q][P] = 0.0f;
#pragma unroll
    for (int k = 0; k < 4; k++) {
        if (k == P || k == Q) continue;
        float mkp = M[k][P], mkq = M[k][Q];
        float np = c * mkp - s * mkq;
        float nq = s * mkp + c * mkq;
        M[k][P] = np; M[P][k] = np;
        M[k][Q] = nq; M[Q][k] = nq;
    }
#pragma unroll
    for (int k = 0; k < 4; k++) {
        float vkp = Vv[k][P], vkq = Vv[k][Q];
        Vv[k][P] = c * vkp - s * vkq;
        Vv[k][Q] = s * vkp + c * vkq;
    }
}

// ---------------- K1 (fused): per-block setup + points + bulk copy ----------
__global__ void fused_k(const float* __restrict__ mk0,
                        const float* __restrict__ mk1,
                        const float* __restrict__ conf,
                        const int*   __restrict__ bids,
                        const float* __restrict__ intr,
                        const float* __restrict__ extr,
                        const float* __restrict__ disps,
                        float*       __restrict__ out)
{
    if (blockIdx.x >= PT_BLOCKS) {
        // ---- copy path ----
        const float4* in4  = (const float4*)disps;
        float4*       out4 = (float4*)out;
        int i = (blockIdx.x - PT_BLOCKS) * blockDim.x + threadIdx.x;
#pragma unroll
        for (int j = 0; j < 4; j++)
            out4[i + j * CP_THREADS] = in4[i + j * CP_THREADS];
        return;
    }

    // ---- per-block setup: 16 (b,v) projection matrices into SMEM ----
    __shared__ float s_proj[BATCH * VIEWS][12];
    __shared__ float s_row2[BATCH * VIEWS][4];
    if (threadIdx.x < BATCH * VIEWS) {
        int i = threadIdx.x;
        // extrinsics are rigid: E = [R t; 0 0 0 1]  =>  inv = [R^T, -R^T t; 0 1]
        double R[3][3], t[3];
        for (int r = 0; r < 3; r++) {
            for (int c = 0; c < 3; c++) R[r][c] = (double)extr[i * 16 + r * 4 + c];
            t[r] = (double)extr[i * 16 + r * 4 + 3];
        }
        double inv[3][4];
        for (int r = 0; r < 3; r++) {
            inv[r][0] = R[0][r]; inv[r][1] = R[1][r]; inv[r][2] = R[2][r];
            inv[r][3] = -(R[0][r] * t[0] + R[1][r] * t[1] + R[2][r] * t[2]);
        }
        double K[3][3];
        for (int r = 0; r < 3; r++)
            for (int c = 0; c < 3; c++)
                K[r][c] = (double)intr[i * 9 + r * 3 + c];
        for (int c = 0; c < 3; c++) { K[0][c] *= (double)WW; K[1][c] *= (double)HH; }
        for (int r = 0; r < 3; r++)
            for (int c = 0; c < 4; c++) {
                double s = K[r][0] * inv[0][c] + K[r][1] * inv[1][c] + K[r][2] * inv[2][c];
                s_proj[i][r * 4 + c] = (float)s;
            }
        for (int c = 0; c < 4; c++) s_row2[i][c] = (float)inv[2][c];
    }
    __syncthreads();

    // ---- point path ----
    int n = blockIdx.x * blockDim.x + threadIdx.x;

    int   b  = bids[n];
    float cf = conf[n];
    float2 p0 = reinterpret_cast<const float2*>(mk0)[n];
    float2 p1 = reinterpret_cast<const float2*>(mk1)[n];

    // prefetch random gathers; their DRAM latency hides under the Jacobi chain.
    int   pix0, pix1;
    float cost0, cost1;
    {
        int x0 = min(max((int)p0.x, 0), WW - 1);
        int y0 = min(max((int)p0.y, 0), HH - 1);
        pix0 = ((b * HH + y0) << 10) + x0;                      // v=0
        int x1 = min(max((int)p1.x, 0), WW - 1);
        int y1 = min(max((int)p1.y, 0), HH - 1);
        pix1 = (((BATCH + b) * HH + y1) << 10) + x1;            // v=1
        cost0 = __ldg(&disps[pix0]);
        cost1 = __ldg(&disps[pix1]);
    }

    const float* P0 = s_proj[b * 2 + 0];
    const float* P1 = s_proj[b * 2 + 1];

    float A[4][4];
#pragma unroll
    for (int k = 0; k < 4; k++) {
        A[0][k] = (P0[8 + k] * p0.x - P0[0 + k]) * cf;
        A[1][k] = (P0[8 + k] * p0.y - P0[4 + k]) * cf;
        A[2][k] = (P1[8 + k] * p1.x - P1[0 + k]) * cf;
        A[3][k] = (P1[8 + k] * p1.y - P1[4 + k]) * cf;
    }

    float M[4][4];
#pragma unroll
    for (int i = 0; i < 4; i++)
#pragma unroll
        for (int j = i; j < 4; j++) {
            float s = A[0][i] * A[0][j];
            s = fmaf(A[1][i], A[1][j], s);
            s = fmaf(A[2][i], A[2][j], s);
            s = fmaf(A[3][i], A[3][j], s);
            M[i][j] = s; M[j][i] = s;
        }

    // relative convergence threshold: eps * trace (trace is rotation-invariant)
    float thr = 1.1920929e-7f * (M[0][0] + M[1][1] + M[2][2] + M[3][3]);

    float Vv[4][4] = {{1,0,0,0},{0,1,0,0},{0,0,1,0},{0,0,0,1}};

#pragma unroll 1
    for (int sweep = 0; sweep < 8; sweep++) {
        jrot<0,1>(M, Vv, thr); jrot<0,2>(M, Vv, thr); jrot<0,3>(M, Vv, thr);
        jrot<1,2>(M, Vv, thr); jrot<1,3>(M, Vv, thr); jrot<2,3>(M, Vv, thr);
    }

    // min-eigenvalue column via static predicated selects (register-resident)
    float dm = M[0][0];
    float h0 = Vv[0][0], h1 = Vv[1][0], h2 = Vv[2][0], h3 = Vv[3][0];
#pragma unroll
    for (int j = 1; j < 4; j++) {
        bool lt = M[j][j] < dm;
        dm = lt ? M[j][j] : dm;
        h0 = lt ? Vv[0][j] : h0;
        h1 = lt ? Vv[1][j] : h1;
        h2 = lt ? Vv[2][j] : h2;
        h3 = lt ? Vv[3][j] : h3;
    }
    float px = h0 / h3, py = h1 / h3, pz = h2 / h3;

    const float* r20 = s_row2[b * 2 + 0];
    const float* r21 = s_row2[b * 2 + 1];
    float z0 = fmaf(r20[0], px, fmaf(r20[1], py, fmaf(r20[2], pz, r20[3])));
    float z1 = fmaf(r21[0], px, fmaf(r21[1], py, fmaf(r21[2], pz, r21[3])));

    bool valid = (z0 > 0.0f) && (z0 < 500.0f) && (z1 > 0.0f) && (z1 < 500.0f);

    // ---- warp-aggregated near/far/has reduction --------------------------
    // g_near/g_far live in ONE 128B line -> ONE LTS slice; per-lane atomics
    // from 131k threads serialized there at ~0.854 cyc/lane (~110us) and were
    // the real limiter (arithmetic changes never moved the kernel time).
    // bids is sorted, so almost every warp is batch-uniform: butterfly-reduce
    // min/max in-warp (identity values = the init values, so merged atomics
    // are value-identical), then ONE lane issues the 4 atomics. Mixed warps
    // (<=7 in the grid) fall back to per-lane atomics.
    {
        unsigned anyv = __ballot_sync(0xffffffffu, valid);
        bool uni = __all_sync(0xffffffffu, __shfl_sync(0xffffffffu, b, 0) == b);
        if (uni) {
            float m0 = valid ? z0 : __int_as_float(0x7f800000);   // +inf
            float m1 = valid ? z1 : __int_as_float(0x7f800000);
            float M0 = valid ? z0 : 0.0f;
            float M1 = valid ? z1 : 0.0f;
#pragma unroll
            for (int o = 16; o > 0; o >>= 1) {
                m0 = fminf(m0, __shfl_xor_sync(0xffffffffu, m0, o));
                m1 = fminf(m1, __shfl_xor_sync(0xffffffffu, m1, o));
                M0 = fmaxf(M0, __shfl_xor_sync(0xffffffffu, M0, o));
                M1 = fmaxf(M1, __shfl_xor_sync(0xffffffffu, M1, o));
            }
            if ((threadIdx.x & 31) == 0 && anyv) {
                atomicMin(&g_near[b * 2 + 0], __float_as_uint(m0));
                atomicMin(&g_near[b * 2 + 1], __float_as_uint(m1));
                atomicMax(&g_far [b * 2 + 0], __float_as_uint(M0));
                atomicMax(&g_far [b * 2 + 1], __float_as_uint(M1));
                g_has[b] = 1;
            }
        } else if (valid) {
            atomicMin(&g_near[b * 2 + 0], __float_as_uint(z0));
            atomicMin(&g_near[b * 2 + 1], __float_as_uint(z1));
            atomicMax(&g_far [b * 2 + 0], __float_as_uint(z0));
            atomicMax(&g_far [b * 2 + 1], __float_as_uint(z1));
            g_has[b] = 1;
        }
    }

    {
        float val0 = valid ? (0.5f * (1.0f / z0) + 0.5f * cost0) : cost0;
        float val1 = valid ? (0.5f * (1.0f / z1) + 0.5f * cost1) : cost1;
        g_val[n * 2 + 0] = val0;
        g_val[n * 2 + 1] = val1;
        g_pix[n * 2 + 0] = pix0;
        g_pix[n * 2 + 1] = pix1;
        g_winner[pix0]   = -1;   // clear only touched pixels
        g_winner[pix1]   = -1;
    }
}

// ---------------- K2: collision winner = max point index --------------------
__global__ void winner_k()
{
    int i = blockIdx.x * blockDim.x + threadIdx.x;
    if (i >= NPTS * 2) return;
    atomicMax(&g_winner[g_pix[i]], i >> 1);
}

// ---------------- K3: scatter winners + near/far/flag tail (+self-reset) ----
__global__ void scatter_final_k(float* __restrict__ out)
{
    int i = blockIdx.x * blockDim.x + threadIdx.x;
    if (i < NPTS * 2) {
        int pix = g_pix[i];
        if (g_winner[pix] == (i >> 1)) out[pix] = g_val[i];
    }
    if (blockIdx.x == 0 && threadIdx.x < BATCH * VIEWS) {
        int t = threadIdx.x;
        int has = g_has[t >> 1];
        out[FUSED_ELEMS +  0 + t] = has ? __uint_as_float(g_near[t]) : 0.0f;
        out[FUSED_ELEMS + 16 + t] = has ? __uint_as_float(g_far[t])  : 500.0f;
        out[FUSED_ELEMS + 32 + t] = has ? 1.0f : 0.0f;
        // restore reset-state invariant for the next graph replay.
        g_near[t] = 0x7f800000u;
        g_far[t]  = 0u;
        if (t < BATCH) g_has[t] = 0;
    }
}

// ---------------- launch -----------------------------------------------------
extern "C" void kernel_launch(void* const* d_in, const int* in_sizes, int n_in,
                              void* d_out, int out_size)
{
    const float* mk0   = (const float*)d_in[0];
    const float* mk1   = (const float*)d_in[1];
    const float* conf  = (const float*)d_in[2];
    const int*   bids  = (const int*)  d_in[3];
    const float* intr  = (const float*)d_in[4];
    const float* extr  = (const float*)d_in[5];
    const float* disps = (const float*)d_in[6];
    float* out = (float*)d_out;

    fused_k        <<<PT_BLOCKS + CP_BLOCKS, 256>>>(mk0, mk1, conf, bids, intr, extr, disps, out);
    winner_k       <<<(NPTS * 2) / 256, 256>>>();
    scatter_final_k<<<(NPTS * 2) / 256, 256>>>(out);
}